// round 2
// baseline (speedup 1.0000x reference)
#include <cuda_runtime.h>
#include <cstdint>
#include <math.h>

// Problem constants
#define BZ     1024
#define DNUM   200
#define FEATD  256
#define HIDD   256
#define MTOT   (BZ*DNUM)        // 204800 tokens
#define NTILES (MTOT/128)       // 1600
#define NCHUNK 16               // 2 sources * (256/32 K-chunks)

// ---------------- device scratch (no allocations allowed) ----------------
// Fragment-major pre-swizzled tf32 weights: [src][kchunk] -> 32KB tile
__device__ uint32_t g_B[2*8*8192];
__device__ float    g_logits[MTOT];

// ---------------- helpers ----------------
__device__ __forceinline__ uint32_t smem_u32(const void* p) {
    uint32_t a;
    asm("{ .reg .u64 t; cvta.to.shared.u64 t, %1; cvt.u32.u64 %0, t; }" : "=r"(a) : "l"(p));
    return a;
}
__device__ __forceinline__ uint32_t tf32_rna(float f) {
    uint32_t r; asm("cvt.rna.tf32.f32 %0, %1;" : "=r"(r) : "f"(f)); return r;
}

#define CP_ASYNC16(dst_u32, src_ptr) \
    asm volatile("cp.async.cg.shared.global [%0], [%1], 16;" :: "r"(dst_u32), "l"(src_ptr) : "memory")
#define CP_COMMIT()  asm volatile("cp.async.commit_group;" ::: "memory")
#define CP_WAIT0()   asm volatile("cp.async.wait_group 0;" ::: "memory")

#define MMA8(d, a, b) \
    asm volatile("mma.sync.aligned.m16n8k8.row.col.f32.tf32.tf32.f32 " \
        "{%0,%1,%2,%3},{%4,%5,%6,%7},{%8,%9},{%0,%1,%2,%3};" \
        : "+f"((d)[0]), "+f"((d)[1]), "+f"((d)[2]), "+f"((d)[3]) \
        : "r"((a).x), "r"((a).y), "r"((a).z), "r"((a).w), "r"((b).x), "r"((b).y))

// smem stage layout: [A fragmajor 16KB][B fragmajor 32KB] x 2 buffers
#define ASTAGE 16384
#define BSTAGE 32768
#define STAGE  (ASTAGE + BSTAGE)
#define SMEM_BYTES (2*STAGE)    // 98304

// ============================================================
// Kernel 0: convert weights to tf32 and store in mma-fragment order.
// For element W[k][n] of source src:  chunk=k>>5, within-chunk k5=k&31:
//   s = k5>>3 (k8 step), tig = k5&3, comp = (k5&7)>>2 (b0/b1)
//   nf = n>>3, g = n&7, lane = g*4+tig
//   dest float offset in 32KB tile = ((s*32+nf)*32+lane)*2 + comp
// ============================================================
__global__ void prep_w_kernel(const float* __restrict__ Wrv, const float* __restrict__ Wid) {
    int idx = blockIdx.x * blockDim.x + threadIdx.x;   // 0..131071
    if (idx >= 2*65536) return;
    int src = idx >> 16;
    int r   = idx & 65535;
    int k   = r >> 8;        // 0..255
    int n   = r & 255;       // 0..255
    const float* W = src ? Wid : Wrv;
    float v = W[k*256 + n];
    int chunk = k >> 5, k5 = k & 31;
    int s = k5 >> 3, tig = k5 & 3, comp = (k5 & 7) >> 2;
    int nf = n >> 3, g = n & 7, lane = g*4 + tig;
    g_B[(src*8 + chunk)*8192 + ((s*32 + nf)*32 + lane)*2 + comp] = tf32_rna(v);
}

// ============================================================
// Kernel 1: fused GEMM (feat@Wrv + ebd@Wid) + bias + relu + dot(h) -> logits
// One CTA per 128-token tile; 8 warps as 2(M) x 4(N); warp tile 64x64.
// ============================================================
__global__ __launch_bounds__(256, 1)
void gemm_logits_kernel(const float4* __restrict__ feat4,
                        const int*    __restrict__ other_id,
                        const float4* __restrict__ ebd4,
                        const float*  __restrict__ b1,
                        const float*  __restrict__ hvec,
                        const float*  __restrict__ b2p)
{
    extern __shared__ char dsm[];
    __shared__ int   ids[128];
    __shared__ float b1s[HIDD];
    __shared__ float hs[HIDD];
    __shared__ float part[128];

    const int tid  = threadIdx.x;
    const int lane = tid & 31;
    const int wid  = tid >> 5;
    const int warp_m = wid >> 2;   // 0..1 (64 rows each)
    const int warp_n = wid & 3;    // 0..3 (64 cols each)
    const int tile = blockIdx.x;

    const uint32_t sbase = smem_u32(dsm);

    if (tid < 128) { ids[tid] = other_id[tile*128 + tid]; part[tid] = 0.f; }
    b1s[tid] = b1[tid];
    hs[tid]  = hvec[tid];

    // staging index decomposition (constant per thread)
    // Each thread handles 4 float4 loads of the 128x32 A chunk.
    float4 areg[4];

    // precompute per-thread A STS float offsets for the 16 scattered stores
    // idx = tid + it*256 ; row = idx>>3 ; q = idx&7 ; col c = q*4+j
    // s=c>>3, cc=c&7, tg=cc&3, half=cc>>2 ; mf=row>>4, rr=row&15, g=rr&7, ab=rr>>3
    // off = ((s*8+mf)*32 + g*4+tg)*4 + half*2+ab
    int a_sts_off[4][4];
    #pragma unroll
    for (int it = 0; it < 4; it++) {
        int idx = tid + it*256;
        int row = idx >> 3, q = idx & 7;
        int mf = row >> 4, rr = row & 15, g = rr & 7, ab = rr >> 3;
        #pragma unroll
        for (int j = 0; j < 4; j++) {
            int c = q*4 + j;
            int s = c >> 3, cc = c & 7, tg = cc & 3, half = cc >> 2;
            a_sts_off[it][j] = ((s*8 + mf)*32 + g*4 + tg)*4 + half*2 + ab;
        }
    }

    // ---- lambdas as macros ----
    #define LDG_A(c_) do {                                                    \
        int src_ = (c_) >> 3, kc_ = (c_) & 7;                                 \
        _Pragma("unroll")                                                     \
        for (int it = 0; it < 4; it++) {                                      \
            int idx = tid + it*256;                                           \
            int row = idx >> 3, q = idx & 7;                                  \
            if (src_ == 0) {                                                  \
                areg[it] = feat4[(size_t)(tile*128 + row)*64 + kc_*8 + q];    \
            } else {                                                          \
                int id_ = ids[row];                                           \
                areg[it] = id_ ? ebd4[(size_t)id_*64 + kc_*8 + q]             \
                               : make_float4(0.f,0.f,0.f,0.f);                \
            }                                                                 \
        }                                                                     \
    } while(0)

    #define STS_A(buf_) do {                                                  \
        uint32_t* As = (uint32_t*)(dsm + (buf_)*STAGE);                       \
        _Pragma("unroll")                                                     \
        for (int it = 0; it < 4; it++) {                                      \
            As[a_sts_off[it][0]] = tf32_rna(areg[it].x);                      \
            As[a_sts_off[it][1]] = tf32_rna(areg[it].y);                      \
            As[a_sts_off[it][2]] = tf32_rna(areg[it].z);                      \
            As[a_sts_off[it][3]] = tf32_rna(areg[it].w);                      \
        }                                                                     \
    } while(0)

    #define CP_B(c_, buf_) do {                                               \
        int src_ = (c_) >> 3, kc_ = (c_) & 7;                                 \
        const char* gsrc = (const char*)(g_B + (src_*8 + kc_)*8192);          \
        uint32_t dstb = sbase + (buf_)*STAGE + ASTAGE;                        \
        _Pragma("unroll")                                                     \
        for (int it = 0; it < 8; it++) {                                      \
            int off = (tid + it*256)*16;                                      \
            CP_ASYNC16(dstb + off, gsrc + off);                               \
        }                                                                     \
        CP_COMMIT();                                                          \
    } while(0)

    float acc[4][8][4];
    #pragma unroll
    for (int i = 0; i < 4; i++)
        #pragma unroll
        for (int j = 0; j < 8; j++)
            #pragma unroll
            for (int t = 0; t < 4; t++) acc[i][j][t] = 0.f;

    // prologue
    LDG_A(0);
    CP_B(0, 0);
    STS_A(0);
    CP_WAIT0();
    __syncthreads();

    for (int c = 0; c < NCHUNK; c++) {
        int buf = c & 1;
        if (c < NCHUNK-1) { LDG_A(c+1); CP_B(c+1, buf^1); }

        // ---- compute one 32-K chunk ----
        {
            const uint4* As = (const uint4*)(dsm + buf*STAGE);
            const uint2* Bs = (const uint2*)(dsm + buf*STAGE + ASTAGE);
            #pragma unroll
            for (int s = 0; s < 4; s++) {
                uint4 af[4];
                #pragma unroll
                for (int i = 0; i < 4; i++)
                    af[i] = As[(s*8 + warp_m*4 + i)*32 + lane];
                uint2 bf[8];
                #pragma unroll
                for (int j = 0; j < 8; j++)
                    bf[j] = Bs[(s*32 + warp_n*8 + j)*32 + lane];
                #pragma unroll
                for (int i = 0; i < 4; i++)
                    #pragma unroll
                    for (int j = 0; j < 8; j++)
                        MMA8(acc[i][j], af[i], bf[j]);
            }
        }

        if (c < NCHUNK-1) { STS_A(buf^1); CP_WAIT0(); }
        __syncthreads();
    }

    // ---- epilogue: logit_row = sum_col relu(acc + b1[col]) * h[col] ----
    {
        const int g   = lane >> 2;
        const int tg  = lane & 3;
        #pragma unroll
        for (int i = 0; i < 4; i++) {
            float p0 = 0.f, p1 = 0.f;
            #pragma unroll
            for (int j = 0; j < 8; j++) {
                int c0 = warp_n*64 + j*8 + tg*2;
                int c1 = c0 + 1;
                float h0 = hs[c0], h1 = hs[c1];
                float bb0 = b1s[c0], bb1 = b1s[c1];
                p0 += fmaxf(acc[i][j][0] + bb0, 0.f) * h0
                    + fmaxf(acc[i][j][1] + bb1, 0.f) * h1;
                p1 += fmaxf(acc[i][j][2] + bb0, 0.f) * h0
                    + fmaxf(acc[i][j][3] + bb1, 0.f) * h1;
            }
            // reduce across the 4 lanes of the row group (tg dimension)
            p0 += __shfl_xor_sync(0xffffffffu, p0, 1);
            p0 += __shfl_xor_sync(0xffffffffu, p0, 2);
            p1 += __shfl_xor_sync(0xffffffffu, p1, 1);
            p1 += __shfl_xor_sync(0xffffffffu, p1, 2);
            if (tg == 0) {
                int r0 = warp_m*64 + i*16 + g;
                atomicAdd(&part[r0],     p0);
                atomicAdd(&part[r0 + 8], p1);
            }
        }
    }
    __syncthreads();
    if (tid < 128) g_logits[tile*128 + tid] = part[tid] + b2p[0];
}

// ============================================================
// Kernel 2: per-batch softmax (faithful: exp / (sum+1e-8)) + weighted sum
// ============================================================
__global__ __launch_bounds__(256)
void softmax_out_kernel(const float* __restrict__ feat,
                        float* __restrict__ out,
                        int write_att)
{
    __shared__ float s[DNUM];
    __shared__ float wsum[8];
    __shared__ float sinv;
    int b = blockIdx.x, tid = threadIdx.x;

    float e = 0.f;
    if (tid < DNUM) { e = __expf(g_logits[b*DNUM + tid]); }
    // NOTE: __expf max rel err ~2^-22 region; use precise expf to be safe
    if (tid < DNUM) { e = expf(g_logits[b*DNUM + tid]); s[tid] = e; }
    float v = e;
    #pragma unroll
    for (int o = 16; o > 0; o >>= 1) v += __shfl_down_sync(0xffffffffu, v, o);
    if ((tid & 31) == 0) wsum[tid >> 5] = v;
    __syncthreads();
    if (tid == 0) {
        float S = 0.f;
        #pragma unroll
        for (int i = 0; i < 8; i++) S += wsum[i];
        sinv = 1.f / (S + 1e-8f);
    }
    __syncthreads();
    float inv = sinv;
    if (tid < DNUM) {
        float sc = s[tid] * inv;
        s[tid] = sc;
        if (write_att) out[BZ*FEATD + b*DNUM + tid] = sc;
    }
    __syncthreads();

    const float* fb = feat + (size_t)b * DNUM * FEATD;
    float acc = 0.f;
    #pragma unroll 4
    for (int d = 0; d < DNUM; d++) acc += s[d] * fb[d*FEATD + tid];
    out[b*FEATD + tid] = acc;
}

// ============================================================
extern "C" void kernel_launch(void* const* d_in, const int* in_sizes, int n_in,
                              void* d_out, int out_size)
{
    const float* feat     = (const float*)d_in[0];
    const int*   other_id = (const int*)  d_in[1];
    const float* Wrv      = (const float*)d_in[2];
    const float* Wid      = (const float*)d_in[3];
    const float* hvec     = (const float*)d_in[4];
    const float* b1       = (const float*)d_in[5];
    const float* b2       = (const float*)d_in[6];
    const float* ebd      = (const float*)d_in[7];
    float* out = (float*)d_out;

    static int configured = 0;
    cudaFuncSetAttribute(gemm_logits_kernel,
                         cudaFuncAttributeMaxDynamicSharedMemorySize, SMEM_BYTES);
    (void)configured;

    prep_w_kernel<<<512, 256>>>(Wrv, Wid);
    gemm_logits_kernel<<<NTILES, 256, SMEM_BYTES>>>(
        (const float4*)feat, other_id, (const float4*)ebd, b1, hvec, b2);

    int write_att = (out_size >= BZ*FEATD + BZ*DNUM) ? 1 : 0;
    softmax_out_kernel<<<BZ, 256>>>(feat, out, write_att);
}

// round 3
// speedup vs baseline: 1.6503x; 1.6503x over previous
#include <cuda_runtime.h>
#include <cuda_fp16.h>
#include <cstdint>
#include <math.h>

// Problem constants
#define BZ     1024
#define DNUM   200
#define FEATD  256
#define HIDD   256
#define MTOT   (BZ*DNUM)        // 204800 tokens
#define NTILES (MTOT/128)       // 1600
#define NCHUNK 16               // 2 sources * (256/32 K-chunks)

// ---------------- device scratch (no allocations allowed) ----------------
// Fragment-major fp16 weights: [src][kchunk] -> 16KB tile (256n x 32k)
__device__ __half g_B[2*8*8192];
__device__ float  g_logits[MTOT];

// ---------------- helpers ----------------
__device__ __forceinline__ uint32_t smem_u32(const void* p) {
    uint32_t a;
    asm("{ .reg .u64 t; cvta.to.shared.u64 t, %1; cvt.u32.u64 %0, t; }" : "=r"(a) : "l"(p));
    return a;
}

#define CP_ASYNC16(dst_u32, src_ptr) \
    asm volatile("cp.async.cg.shared.global [%0], [%1], 16;" :: "r"(dst_u32), "l"(src_ptr) : "memory")
#define CP_COMMIT()  asm volatile("cp.async.commit_group;" ::: "memory")
#define CP_WAIT0()   asm volatile("cp.async.wait_group 0;" ::: "memory")

// m16n8k16 fp16 MMA, fp32 accumulate
#define MMA16(d, a, b) \
    asm volatile("mma.sync.aligned.m16n8k16.row.col.f32.f16.f16.f32 " \
        "{%0,%1,%2,%3},{%4,%5,%6,%7},{%8,%9},{%0,%1,%2,%3};" \
        : "+f"((d)[0]), "+f"((d)[1]), "+f"((d)[2]), "+f"((d)[3]) \
        : "r"((a).x), "r"((a).y), "r"((a).z), "r"((a).w), "r"((b).x), "r"((b).y))

// smem stage layout: [A fragmajor 8KB][B fragmajor 16KB] x 2 buffers
#define ASTAGE 8192
#define BSTAGE 16384
#define STAGE  (ASTAGE + BSTAGE)
#define SMEM_BYTES (2*STAGE)    // 49152

// ============================================================
// Kernel 0: convert weights to fp16 in mma-fragment order.
// Fragment layout for B (col-major k16 x n8, m16n8k16):
//   lane = g*4 + tg where g = n&7, tg = (kk>>1)&3 ; kk = k within 16
//   uint2 per lane: comp = kh (kk>>3), halfword = kbit (kk&1)
// Tile half-index: ((s*32+nf)*32 + lane)*4 + kh*2 + kbit
//   s = (k&31)>>4 (k16 step), nf = n>>3
// ============================================================
__global__ void prep_w_kernel(const float* __restrict__ Wrv, const float* __restrict__ Wid) {
    int idx = blockIdx.x * blockDim.x + threadIdx.x;   // 0..131071
    if (idx >= 2*65536) return;
    int src = idx >> 16;
    int r   = idx & 65535;
    int k   = r >> 8;        // 0..255
    int n   = r & 255;       // 0..255
    const float* W = src ? Wid : Wrv;
    float v = W[k*256 + n];
    int chunk = k >> 5, k5 = k & 31;
    int s = k5 >> 4, kk = k5 & 15;
    int tg = (kk >> 1) & 3, kh = kk >> 3, kbit = kk & 1;
    int nf = n >> 3, g = n & 7, lane = g*4 + tg;
    g_B[(src*8 + chunk)*8192 + ((s*32 + nf)*32 + lane)*4 + kh*2 + kbit] = __float2half(v);
}

// ============================================================
// Kernel 1: fused GEMM (feat@Wrv + ebd@Wid) + bias + relu + dot(h) -> logits
// One CTA per 128-token tile; 8 warps as 2(M) x 4(N); warp tile 64x64.
// ============================================================
__global__ __launch_bounds__(256, 1)
void gemm_logits_kernel(const float4* __restrict__ feat4,
                        const int*    __restrict__ other_id,
                        const float4* __restrict__ ebd4,
                        const float*  __restrict__ b1,
                        const float*  __restrict__ hvec,
                        const float*  __restrict__ b2p)
{
    extern __shared__ char dsm[];
    __shared__ int   ids[128];
    __shared__ float b1s[HIDD];
    __shared__ float hs[HIDD];
    __shared__ float part[128];

    const int tid  = threadIdx.x;
    const int lane = tid & 31;
    const int wid  = tid >> 5;
    const int warp_m = wid >> 2;   // 0..1 (64 rows each)
    const int warp_n = wid & 3;    // 0..3 (64 cols each)
    const int tile = blockIdx.x;

    const uint32_t sbase = smem_u32(dsm);

    if (tid < 128) { ids[tid] = other_id[tile*128 + tid]; part[tid] = 0.f; }
    b1s[tid] = b1[tid];
    hs[tid]  = hvec[tid];

    float4 areg[4];

    // Per-thread A STS word offsets. Thread handles float4 at (row, q):
    //   k = 4q..4q+3 ; s=q>>2 ; kh=(q>>1)&1 ; mf=row>>4 ; rr=row&15
    //   g=rr&7 ; ab=rr>>3 ; comp = kh*2+ab
    //   pair (x,y) -> lane slot g*4 + 2*(q&1) ; pair (z,w) -> +1
    int a_sts_off[4][2];
    #pragma unroll
    for (int it = 0; it < 4; it++) {
        int idx = tid + it*256;
        int row = idx >> 3, q = idx & 7;
        int s = q >> 2, kh = (q >> 1) & 1;
        int mf = row >> 4, rr = row & 15, g = rr & 7, ab = rr >> 3;
        int comp = kh*2 + ab;
        int lane0 = g*4 + 2*(q & 1);
        a_sts_off[it][0] = ((s*8 + mf)*32 + lane0)*4 + comp;
        a_sts_off[it][1] = ((s*8 + mf)*32 + lane0 + 1)*4 + comp;
    }

    #define LDG_A(c_) do {                                                    \
        int src_ = (c_) >> 3, kc_ = (c_) & 7;                                 \
        _Pragma("unroll")                                                     \
        for (int it = 0; it < 4; it++) {                                      \
            int idx = tid + it*256;                                           \
            int row = idx >> 3, q = idx & 7;                                  \
            if (src_ == 0) {                                                  \
                areg[it] = feat4[(size_t)(tile*128 + row)*64 + kc_*8 + q];    \
            } else {                                                          \
                int id_ = ids[row];                                           \
                areg[it] = id_ ? ebd4[(size_t)id_*64 + kc_*8 + q]             \
                               : make_float4(0.f,0.f,0.f,0.f);                \
            }                                                                 \
        }                                                                     \
    } while(0)

    #define STS_A(buf_) do {                                                  \
        uint32_t* As = (uint32_t*)(dsm + (buf_)*STAGE);                       \
        _Pragma("unroll")                                                     \
        for (int it = 0; it < 4; it++) {                                      \
            __half2 p0 = __floats2half2_rn(areg[it].x, areg[it].y);           \
            __half2 p1 = __floats2half2_rn(areg[it].z, areg[it].w);           \
            As[a_sts_off[it][0]] = *(uint32_t*)&p0;                           \
            As[a_sts_off[it][1]] = *(uint32_t*)&p1;                           \
        }                                                                     \
    } while(0)

    #define CP_B(c_, buf_) do {                                               \
        int src_ = (c_) >> 3, kc_ = (c_) & 7;                                 \
        const char* gsrc = (const char*)(g_B + (src_*8 + kc_)*8192);          \
        uint32_t dstb = sbase + (buf_)*STAGE + ASTAGE;                        \
        _Pragma("unroll")                                                     \
        for (int it = 0; it < 4; it++) {                                      \
            int off = (tid + it*256)*16;                                      \
            CP_ASYNC16(dstb + off, gsrc + off);                               \
        }                                                                     \
        CP_COMMIT();                                                          \
    } while(0)

    float acc[4][8][4];
    #pragma unroll
    for (int i = 0; i < 4; i++)
        #pragma unroll
        for (int j = 0; j < 8; j++)
            #pragma unroll
            for (int t = 0; t < 4; t++) acc[i][j][t] = 0.f;

    // prologue
    LDG_A(0);
    CP_B(0, 0);
    STS_A(0);
    CP_WAIT0();
    __syncthreads();

    for (int c = 0; c < NCHUNK; c++) {
        int buf = c & 1;
        if (c < NCHUNK-1) { LDG_A(c+1); CP_B(c+1, buf^1); }

        // ---- compute one 32-K chunk (2 k16 steps) ----
        {
            const uint4* As = (const uint4*)(dsm + buf*STAGE);
            const uint2* Bs = (const uint2*)(dsm + buf*STAGE + ASTAGE);
            #pragma unroll
            for (int s = 0; s < 2; s++) {
                uint4 af[4];
                #pragma unroll
                for (int i = 0; i < 4; i++)
                    af[i] = As[(s*8 + warp_m*4 + i)*32 + lane];
                uint2 bf[8];
                #pragma unroll
                for (int j = 0; j < 8; j++)
                    bf[j] = Bs[(s*32 + warp_n*8 + j)*32 + lane];
                #pragma unroll
                for (int i = 0; i < 4; i++)
                    #pragma unroll
                    for (int j = 0; j < 8; j++)
                        MMA16(acc[i][j], af[i], bf[j]);
            }
        }

        if (c < NCHUNK-1) { STS_A(buf^1); CP_WAIT0(); }
        __syncthreads();
    }

    // ---- epilogue: logit_row = sum_col relu(acc + b1[col]) * h[col] ----
    {
        const int g   = lane >> 2;
        const int tg  = lane & 3;
        #pragma unroll
        for (int i = 0; i < 4; i++) {
            float p0 = 0.f, p1 = 0.f;
            #pragma unroll
            for (int j = 0; j < 8; j++) {
                int c0 = warp_n*64 + j*8 + tg*2;
                int c1 = c0 + 1;
                float h0 = hs[c0], h1 = hs[c1];
                float bb0 = b1s[c0], bb1 = b1s[c1];
                p0 += fmaxf(acc[i][j][0] + bb0, 0.f) * h0
                    + fmaxf(acc[i][j][1] + bb1, 0.f) * h1;
                p1 += fmaxf(acc[i][j][2] + bb0, 0.f) * h0
                    + fmaxf(acc[i][j][3] + bb1, 0.f) * h1;
            }
            p0 += __shfl_xor_sync(0xffffffffu, p0, 1);
            p0 += __shfl_xor_sync(0xffffffffu, p0, 2);
            p1 += __shfl_xor_sync(0xffffffffu, p1, 1);
            p1 += __shfl_xor_sync(0xffffffffu, p1, 2);
            if (tg == 0) {
                int r0 = warp_m*64 + i*16 + g;
                atomicAdd(&part[r0],     p0);
                atomicAdd(&part[r0 + 8], p1);
            }
        }
    }
    __syncthreads();
    if (tid < 128) g_logits[tile*128 + tid] = part[tid] + b2p[0];
}

// ============================================================
// Kernel 2: per-batch softmax (faithful: exp / (sum+1e-8)) + weighted sum
// ============================================================
__global__ __launch_bounds__(256)
void softmax_out_kernel(const float* __restrict__ feat,
                        float* __restrict__ out,
                        int write_att)
{
    __shared__ float s[DNUM];
    __shared__ float wsum[8];
    __shared__ float sinv;
    int b = blockIdx.x, tid = threadIdx.x;

    float e = 0.f;
    if (tid < DNUM) { e = expf(g_logits[b*DNUM + tid]); s[tid] = e; }
    float v = e;
    #pragma unroll
    for (int o = 16; o > 0; o >>= 1) v += __shfl_down_sync(0xffffffffu, v, o);
    if ((tid & 31) == 0) wsum[tid >> 5] = v;
    __syncthreads();
    if (tid == 0) {
        float S = 0.f;
        #pragma unroll
        for (int i = 0; i < 8; i++) S += wsum[i];
        sinv = 1.f / (S + 1e-8f);
    }
    __syncthreads();
    float inv = sinv;
    if (tid < DNUM) {
        float sc = s[tid] * inv;
        s[tid] = sc;
        if (write_att) out[BZ*FEATD + b*DNUM + tid] = sc;
    }
    __syncthreads();

    const float* fb = feat + (size_t)b * DNUM * FEATD;
    float acc = 0.f;
    #pragma unroll 4
    for (int d = 0; d < DNUM; d++) acc += s[d] * fb[d*FEATD + tid];
    out[b*FEATD + tid] = acc;
}

// ============================================================
extern "C" void kernel_launch(void* const* d_in, const int* in_sizes, int n_in,
                              void* d_out, int out_size)
{
    const float* feat     = (const float*)d_in[0];
    const int*   other_id = (const int*)  d_in[1];
    const float* Wrv      = (const float*)d_in[2];
    const float* Wid      = (const float*)d_in[3];
    const float* hvec     = (const float*)d_in[4];
    const float* b1       = (const float*)d_in[5];
    const float* b2       = (const float*)d_in[6];
    const float* ebd      = (const float*)d_in[7];
    float* out = (float*)d_out;

    cudaFuncSetAttribute(gemm_logits_kernel,
                         cudaFuncAttributeMaxDynamicSharedMemorySize, SMEM_BYTES);

    prep_w_kernel<<<512, 256>>>(Wrv, Wid);
    gemm_logits_kernel<<<NTILES, 256, SMEM_BYTES>>>(
        (const float4*)feat, other_id, (const float4*)ebd, b1, hvec, b2);

    int write_att = (out_size >= BZ*FEATD + BZ*DNUM) ? 1 : 0;
    softmax_out_kernel<<<BZ, 256>>>(feat, out, write_att);
}

// round 4
// speedup vs baseline: 1.7578x; 1.0651x over previous
#include <cuda_runtime.h>
#include <cuda_fp16.h>
#include <cstdint>
#include <math.h>

// Problem constants
#define BZ     1024
#define DNUM   200
#define FEATD  256
#define HIDD   256
#define MTOT   (BZ*DNUM)        // 204800 tokens
#define TILE_M 64
#define NTILES (MTOT/TILE_M)    // 3200
#define NCHUNK 16               // 2 sources * (256/32 K-chunks)

// ---------------- device scratch (no allocations allowed) ----------------
// Fragment-major fp16 weights: [src][kchunk] -> 16KB tile (256n x 32k)
__device__ __half g_B[2*8*8192];
__device__ float  g_logits[MTOT];

// ---------------- helpers ----------------
__device__ __forceinline__ uint32_t smem_u32(const void* p) {
    uint32_t a;
    asm("{ .reg .u64 t; cvta.to.shared.u64 t, %1; cvt.u32.u64 %0, t; }" : "=r"(a) : "l"(p));
    return a;
}

#define CP_ASYNC16(dst_u32, src_ptr) \
    asm volatile("cp.async.cg.shared.global [%0], [%1], 16;" :: "r"(dst_u32), "l"(src_ptr) : "memory")
#define CP_COMMIT()  asm volatile("cp.async.commit_group;" ::: "memory")
#define CP_WAIT0()   asm volatile("cp.async.wait_group 0;" ::: "memory")

// m16n8k16 fp16 MMA, fp32 accumulate
#define MMA16(d, a, b) \
    asm volatile("mma.sync.aligned.m16n8k16.row.col.f32.f16.f16.f32 " \
        "{%0,%1,%2,%3},{%4,%5,%6,%7},{%8,%9},{%0,%1,%2,%3};" \
        : "+f"((d)[0]), "+f"((d)[1]), "+f"((d)[2]), "+f"((d)[3]) \
        : "r"((a).x), "r"((a).y), "r"((a).z), "r"((a).w), "r"((b).x), "r"((b).y))

// smem stage: [A fragmajor 4KB][B fragmajor 16KB] x 2 buffers
#define ASTAGE 4096
#define BSTAGE 16384
#define STAGE  (ASTAGE + BSTAGE)
#define SMEM_BYTES (2*STAGE)    // 40960

// ============================================================
// Kernel 0: convert weights to fp16 in mma-fragment order (unchanged).
// ============================================================
__global__ void prep_w_kernel(const float* __restrict__ Wrv, const float* __restrict__ Wid) {
    int idx = blockIdx.x * blockDim.x + threadIdx.x;   // 0..131071
    if (idx >= 2*65536) return;
    int src = idx >> 16;
    int r   = idx & 65535;
    int k   = r >> 8;        // 0..255
    int n   = r & 255;       // 0..255
    const float* W = src ? Wid : Wrv;
    float v = W[k*256 + n];
    int chunk = k >> 5, k5 = k & 31;
    int s = k5 >> 4, kk = k5 & 15;
    int tg = (kk >> 1) & 3, kh = kk >> 3, kbit = kk & 1;
    int nf = n >> 3, g = n & 7, lane = g*4 + tg;
    g_B[(src*8 + chunk)*8192 + ((s*32 + nf)*32 + lane)*4 + kh*2 + kbit] = __float2half(v);
}

// ============================================================
// Kernel 1: fused GEMM (feat@Wrv + ebd@Wid) + bias + relu + dot(h) -> logits
// CTA tile 64 tokens x 256 hid; 8 warps as 2(M:32) x 4(N:64); 2 CTAs/SM.
// ============================================================
__global__ __launch_bounds__(256, 2)
void gemm_logits_kernel(const float4* __restrict__ feat4,
                        const int*    __restrict__ other_id,
                        const float4* __restrict__ ebd4,
                        const float*  __restrict__ b1,
                        const float*  __restrict__ hvec,
                        const float*  __restrict__ b2p)
{
    extern __shared__ char dsm[];
    __shared__ int   ids[TILE_M];
    __shared__ float b1s[HIDD];
    __shared__ float hs[HIDD];
    __shared__ float part[TILE_M];

    const int tid  = threadIdx.x;
    const int lane = tid & 31;
    const int wid  = tid >> 5;
    const int warp_m = wid >> 2;   // 0..1 (32 rows each)
    const int warp_n = wid & 3;    // 0..3 (64 cols each)
    const int tile = blockIdx.x;

    const uint32_t sbase = smem_u32(dsm);

    if (tid < TILE_M) { ids[tid] = other_id[tile*TILE_M + tid]; part[tid] = 0.f; }
    b1s[tid] = b1[tid];
    hs[tid]  = hvec[tid];

    float4 areg[2];

    // Per-thread A STS word offsets (2 float4 per thread covering 64x32 chunk)
    // idx = tid + it*256 in 0..511 ; row = idx>>3 (0..63) ; q = idx&7
    // s=q>>2 ; kh=(q>>1)&1 ; mf=row>>4 (0..3) ; rr=row&15 ; g=rr&7 ; ab=rr>>3
    // comp = kh*2+ab ; lane0 = g*4 + 2*(q&1)
    // word off = ((s*4+mf)*32 + lane0 + {0,1})*4 + comp
    int a_sts_off[2][2];
    #pragma unroll
    for (int it = 0; it < 2; it++) {
        int idx = tid + it*256;
        int row = idx >> 3, q = idx & 7;
        int s = q >> 2, kh = (q >> 1) & 1;
        int mf = row >> 4, rr = row & 15, g = rr & 7, ab = rr >> 3;
        int comp = kh*2 + ab;
        int lane0 = g*4 + 2*(q & 1);
        a_sts_off[it][0] = ((s*4 + mf)*32 + lane0)*4 + comp;
        a_sts_off[it][1] = ((s*4 + mf)*32 + lane0 + 1)*4 + comp;
    }

    #define LDG_A(c_) do {                                                    \
        int src_ = (c_) >> 3, kc_ = (c_) & 7;                                 \
        _Pragma("unroll")                                                     \
        for (int it = 0; it < 2; it++) {                                      \
            int idx = tid + it*256;                                           \
            int row = idx >> 3, q = idx & 7;                                  \
            if (src_ == 0) {                                                  \
                areg[it] = feat4[(size_t)(tile*TILE_M + row)*64 + kc_*8 + q]; \
            } else {                                                          \
                int id_ = ids[row];                                           \
                areg[it] = id_ ? ebd4[(size_t)id_*64 + kc_*8 + q]             \
                               : make_float4(0.f,0.f,0.f,0.f);                \
            }                                                                 \
        }                                                                     \
    } while(0)

    #define STS_A(buf_) do {                                                  \
        uint32_t* As = (uint32_t*)(dsm + (buf_)*STAGE);                       \
        _Pragma("unroll")                                                     \
        for (int it = 0; it < 2; it++) {                                      \
            __half2 p0 = __floats2half2_rn(areg[it].x, areg[it].y);           \
            __half2 p1 = __floats2half2_rn(areg[it].z, areg[it].w);           \
            As[a_sts_off[it][0]] = *(uint32_t*)&p0;                           \
            As[a_sts_off[it][1]] = *(uint32_t*)&p1;                           \
        }                                                                     \
    } while(0)

    #define CP_B(c_, buf_) do {                                               \
        int src_ = (c_) >> 3, kc_ = (c_) & 7;                                 \
        const char* gsrc = (const char*)(g_B + (src_*8 + kc_)*8192);          \
        uint32_t dstb = sbase + (buf_)*STAGE + ASTAGE;                        \
        _Pragma("unroll")                                                     \
        for (int it = 0; it < 4; it++) {                                      \
            int off = (tid + it*256)*16;                                      \
            CP_ASYNC16(dstb + off, gsrc + off);                               \
        }                                                                     \
        CP_COMMIT();                                                          \
    } while(0)

    float acc[2][8][4];
    #pragma unroll
    for (int i = 0; i < 2; i++)
        #pragma unroll
        for (int j = 0; j < 8; j++)
            #pragma unroll
            for (int t = 0; t < 4; t++) acc[i][j][t] = 0.f;

    // prologue
    LDG_A(0);
    CP_B(0, 0);
    STS_A(0);
    CP_WAIT0();
    __syncthreads();

    for (int c = 0; c < NCHUNK; c++) {
        int buf = c & 1;
        if (c < NCHUNK-1) { LDG_A(c+1); CP_B(c+1, buf^1); }

        // ---- compute one 32-K chunk (2 k16 steps) ----
        {
            const uint4* As = (const uint4*)(dsm + buf*STAGE);
            const uint2* Bs = (const uint2*)(dsm + buf*STAGE + ASTAGE);
            #pragma unroll
            for (int s = 0; s < 2; s++) {
                uint4 af[2];
                #pragma unroll
                for (int i = 0; i < 2; i++)
                    af[i] = As[(s*4 + warp_m*2 + i)*32 + lane];
                uint2 bf[8];
                #pragma unroll
                for (int j = 0; j < 8; j++)
                    bf[j] = Bs[(s*32 + warp_n*8 + j)*32 + lane];
                #pragma unroll
                for (int i = 0; i < 2; i++)
                    #pragma unroll
                    for (int j = 0; j < 8; j++)
                        MMA16(acc[i][j], af[i], bf[j]);
            }
        }

        if (c < NCHUNK-1) { STS_A(buf^1); CP_WAIT0(); }
        __syncthreads();
    }

    // ---- epilogue: logit_row = sum_col relu(acc + b1[col]) * h[col] ----
    {
        const int g   = lane >> 2;
        const int tg  = lane & 3;
        #pragma unroll
        for (int i = 0; i < 2; i++) {
            float p0 = 0.f, p1 = 0.f;
            #pragma unroll
            for (int j = 0; j < 8; j++) {
                int c0 = warp_n*64 + j*8 + tg*2;
                int c1 = c0 + 1;
                float h0 = hs[c0], h1 = hs[c1];
                float bb0 = b1s[c0], bb1 = b1s[c1];
                p0 += fmaxf(acc[i][j][0] + bb0, 0.f) * h0
                    + fmaxf(acc[i][j][1] + bb1, 0.f) * h1;
                p1 += fmaxf(acc[i][j][2] + bb0, 0.f) * h0
                    + fmaxf(acc[i][j][3] + bb1, 0.f) * h1;
            }
            p0 += __shfl_xor_sync(0xffffffffu, p0, 1);
            p0 += __shfl_xor_sync(0xffffffffu, p0, 2);
            p1 += __shfl_xor_sync(0xffffffffu, p1, 1);
            p1 += __shfl_xor_sync(0xffffffffu, p1, 2);
            if (tg == 0) {
                int r0 = warp_m*32 + i*16 + g;
                atomicAdd(&part[r0],     p0);
                atomicAdd(&part[r0 + 8], p1);
            }
        }
    }
    __syncthreads();
    if (tid < TILE_M) g_logits[tile*TILE_M + tid] = part[tid] + b2p[0];
}

// ============================================================
// Kernel 2: per-batch softmax (faithful: exp / (sum+1e-8)) + weighted sum
// ============================================================
__global__ __launch_bounds__(256)
void softmax_out_kernel(const float* __restrict__ feat,
                        float* __restrict__ out,
                        int write_att)
{
    __shared__ float s[DNUM];
    __shared__ float wsum[8];
    __shared__ float sinv;
    int b = blockIdx.x, tid = threadIdx.x;

    float e = 0.f;
    if (tid < DNUM) { e = expf(g_logits[b*DNUM + tid]); s[tid] = e; }
    float v = e;
    #pragma unroll
    for (int o = 16; o > 0; o >>= 1) v += __shfl_down_sync(0xffffffffu, v, o);
    if ((tid & 31) == 0) wsum[tid >> 5] = v;
    __syncthreads();
    if (tid == 0) {
        float S = 0.f;
        #pragma unroll
        for (int i = 0; i < 8; i++) S += wsum[i];
        sinv = 1.f / (S + 1e-8f);
    }
    __syncthreads();
    float inv = sinv;
    if (tid < DNUM) {
        float sc = s[tid] * inv;
        s[tid] = sc;
        if (write_att) out[BZ*FEATD + b*DNUM + tid] = sc;
    }
    __syncthreads();

    const float* fb = feat + (size_t)b * DNUM * FEATD;
    float acc = 0.f;
    #pragma unroll 4
    for (int d = 0; d < DNUM; d++) acc += s[d] * fb[d*FEATD + tid];
    out[b*FEATD + tid] = acc;
}

// ============================================================
extern "C" void kernel_launch(void* const* d_in, const int* in_sizes, int n_in,
                              void* d_out, int out_size)
{
    const float* feat     = (const float*)d_in[0];
    const int*   other_id = (const int*)  d_in[1];
    const float* Wrv      = (const float*)d_in[2];
    const float* Wid      = (const float*)d_in[3];
    const float* hvec     = (const float*)d_in[4];
    const float* b1       = (const float*)d_in[5];
    const float* b2       = (const float*)d_in[6];
    const float* ebd      = (const float*)d_in[7];
    float* out = (float*)d_out;

    cudaFuncSetAttribute(gemm_logits_kernel,
                         cudaFuncAttributeMaxDynamicSharedMemorySize, SMEM_BYTES);

    prep_w_kernel<<<512, 256>>>(Wrv, Wid);
    gemm_logits_kernel<<<NTILES, 256, SMEM_BYTES>>>(
        (const float4*)feat, other_id, (const float4*)ebd, b1, hvec, b2);

    int write_att = (out_size >= BZ*FEATD + BZ*DNUM) ? 1 : 0;
    softmax_out_kernel<<<BZ, 256>>>(feat, out, write_att);
}